// round 12
// baseline (speedup 1.0000x reference)
#include <cuda_runtime.h>
#include <math.h>

#define B_N     16
#define C_CH    256
#define L_LEN   8192
#define DEPTH_N 12

#define NTH     256
#define NSLOT   16             // pairs per thread
#define SM_STRIDE 8704         // floats per buffer (8192 + 2 pad per 32 floats)
#define BUFB    (SM_STRIDE * 4)

using u64 = unsigned long long;

// padded relative word offset for element index e (may be < 0): e + 2*floor(e/32)
__host__ __device__ constexpr int padrel(int e) {
    int q = (e >= 0) ? (e / 32) : -(((31 - e) / 32));
    return e + 2 * q;
}

__device__ __forceinline__ u64 pk2(float lo, float hi) {
    u64 r; asm("mov.b64 %0,{%1,%2};" : "=l"(r) : "f"(lo), "f"(hi)); return r;
}
__device__ __forceinline__ void upk2(u64 v, float& lo, float& hi) {
    asm("mov.b64 {%0,%1},%2;" : "=f"(lo), "=f"(hi) : "l"(v));
}
__device__ __forceinline__ u64 fma2(u64 a, u64 b, u64 c) {
    u64 r; asm("fma.rn.f32x2 %0,%1,%2,%3;" : "=l"(r) : "l"(a), "l"(b), "l"(c)); return r;
}
__device__ __forceinline__ u64 mul2(u64 a, u64 b) {
    u64 r; asm("mul.rn.f32x2 %0,%1,%2;" : "=l"(r) : "l"(a), "l"(b)); return r;
}
// GELU via tanh-form with HW tanh.approx (1 MUFU op vs ~30-instr erff):
// gelu(x) = 0.5x(1 + tanh(0.79788456(x + 0.044715 x^3)))
__device__ __forceinline__ float gelu_t(float x) {
    float s = x * fmaf(x * x, 0.044715f * 0.7978845608028654f, 0.7978845608028654f);
    float t; asm("tanh.approx.f32 %0,%1;" : "=f"(t) : "f"(s));
    return 0.5f * x * (1.0f + t);
}

// ---------- Phase A: block layout (thread owns pairs 16t..16t+15) ----------
template<int DD, int SF>
__device__ __forceinline__ void levelA(
    u64 (&rl)[NSLOT], u64 (&y2)[NSLOT], const char* ob, char* nb,
    bool ge1, bool ge2,
    u64 a0, u64 a1, u64 a2, u64 a3,
    u64 b0, u64 b1, u64 b2, u64 b3)
{
    __syncthreads();   // previous level's smem writes visible
#pragma unroll
    for (int p = NSLOT - 1; p >= 0; --p) {
        u64 t0 = rl[p];
        u64 t1, t2, t3;
        if (p >= 1 * DD) t1 = rl[p - 1 * DD];
        else { bool ok = ((1 * DD - p + 15) / 16 <= 1) ? ge1 : ge2;
               t1 = ok ? *(const u64*)(ob + 4 * padrel(2 * (p - 1 * DD))) : 0; }
        if (p >= 2 * DD) t2 = rl[p - 2 * DD];
        else { bool ok = ((2 * DD - p + 15) / 16 <= 1) ? ge1 : ge2;
               t2 = ok ? *(const u64*)(ob + 4 * padrel(2 * (p - 2 * DD))) : 0; }
        if (p >= 3 * DD) t3 = rl[p - 3 * DD];
        else { bool ok = ((3 * DD - p + 15) / 16 <= 1) ? ge1 : ge2;
               t3 = ok ? *(const u64*)(ob + 4 * padrel(2 * (p - 3 * DD))) : 0; }
        y2[p] = fma2(b3, t0, fma2(b2, t1, fma2(b1, t2, fma2(b0, t3, y2[p]))));
        rl[p] = fma2(a3, t0, fma2(a2, t1, fma2(a1, t2, mul2(a0, t3))));
    }
#pragma unroll
    for (int p = SF; p < NSLOT; ++p)
        *(u64*)(nb + 8 * p) = rl[p];
}

// ---------- Phase B: tile16 layout (thread (T,r) owns pairs 256T + r + 16j) ----------
template<int DJ, int SF, bool STORE>
__device__ __forceinline__ void levelB(
    u64 (&rl)[NSLOT], u64 (&y2)[NSLOT], const char* ob, char* nb,
    bool tge1, bool tge2,
    u64 a0, u64 a1, u64 a2, u64 a3,
    u64 b0, u64 b1, u64 b2, u64 b3)
{
    __syncthreads();
#pragma unroll
    for (int j = NSLOT - 1; j >= 0; --j) {
        u64 t0 = rl[j];
        u64 t1, t2, t3;
        if (j >= 1 * DJ) t1 = rl[j - 1 * DJ];
        else { bool ok = (1 * DJ - j <= 16) ? tge1 : tge2;
               t1 = ok ? *(const u64*)(ob + 136 * (j - 1 * DJ)) : 0; }
        if (j >= 2 * DJ) t2 = rl[j - 2 * DJ];
        else { bool ok = (2 * DJ - j <= 16) ? tge1 : tge2;
               t2 = ok ? *(const u64*)(ob + 136 * (j - 2 * DJ)) : 0; }
        if (j >= 3 * DJ) t3 = rl[j - 3 * DJ];
        else { bool ok = (3 * DJ - j <= 16) ? tge1 : tge2;
               t3 = ok ? *(const u64*)(ob + 136 * (j - 3 * DJ)) : 0; }
        y2[j] = fma2(b3, t0, fma2(b2, t1, fma2(b1, t2, fma2(b0, t3, y2[j]))));
        rl[j] = fma2(a3, t0, fma2(a2, t1, fma2(a1, t2, mul2(a0, t3))));
    }
    if (STORE) {
#pragma unroll
        for (int j = SF; j < NSLOT; ++j)
            *(u64*)(nb + 136 * j) = rl[j];
    }
}

// ---------- Phase C: cyclic-256 layout (pure register, no smem, no sync) ----------
template<int DK>
__device__ __forceinline__ void levelC(
    u64 (&rl)[NSLOT], u64 (&y2)[NSLOT],
    u64 a0, u64 a1, u64 a2, u64 a3,
    u64 b0, u64 b1, u64 b2, u64 b3)
{
#pragma unroll
    for (int k = NSLOT - 1; k >= 0; --k) {
        u64 t0 = rl[k];
        u64 t1 = (k >= 1 * DK) ? rl[k - 1 * DK] : 0;
        u64 t2 = (k >= 2 * DK) ? rl[k - 2 * DK] : 0;
        u64 t3 = (k >= 3 * DK) ? rl[k - 3 * DK] : 0;
        y2[k] = fma2(b3, t0, fma2(b2, t1, fma2(b1, t2, fma2(b0, t3, y2[k]))));
        rl[k] = fma2(a3, t0, fma2(a2, t1, fma2(a1, t2, mul2(a0, t3))));
    }
}

__global__ void __launch_bounds__(NTH, 3)
mr_kernel(const float* __restrict__ x, const float* __restrict__ h0,
          const float* __restrict__ h1, const float* __restrict__ w,
          float* __restrict__ out)
{
    extern __shared__ float sm[];
    char* B0 = (char*)sm;
    char* B1 = (char*)sm + BUFB;
    float* scr = (float*)((char*)sm + 2 * BUFB);   // 8 warps x 3 floats

    const int tid  = threadIdx.x;
    const int lane = tid & 31;
    const int warp = tid >> 5;
    const int T    = tid >> 4;        // tile index (tile16 layout)
    const int rr   = tid & 15;        // lane-in-tile
    const int row  = blockIdx.x;      // b*C + c
    const int c    = row & (C_CH - 1);
    const float* xr   = x   + (size_t)row * L_LEN;
    float*       outr = out + (size_t)row * L_LEN;

    const bool ge1  = (tid >= 1), ge2 = (tid >= 2);
    const bool tge1 = (T >= 1),  tge2 = (T >= 2);

    char* blk0 = B0 + 136 * tid;
    char* blk1 = B1 + 136 * tid;
    char* til0 = B0 + 2176 * T + 8 * rr;
    char* til1 = B1 + 2176 * T + 8 * rr;
    char* cyc0 = B0 + 8 * tid + 8 * (tid >> 4);
    char* cyc1 = B1 + 8 * tid + 8 * (tid >> 4);

    // ---- load own 32 elements directly as 16 f32x2 pairs ----
    u64 rl[NSLOT], y2[NSLOT];
    u64 xp[NSLOT];
    {
        const float4* x4 = (const float4*)xr + tid * 8;
#pragma unroll
        for (int i = 0; i < 8; ++i) {
            float4 v = x4[i];
            xp[2 * i]     = pk2(v.x, v.y);
            xp[2 * i + 1] = pk2(v.z, v.w);
        }
    }
    {
        float l14, h14, l15, h15;
        upk2(xp[14], l14, h14);
        upk2(xp[15], l15, h15);
        if (lane == 31) {                 // cross-warp x halo for d=1
            scr[3 * warp + 0] = h14;      // x[29]
            scr[3 * warp + 1] = l15;      // x[30]
            scr[3 * warp + 2] = h15;      // x[31]
        }
    }

    // ---- per-channel coefficients ----
    const float c0 = __ldg(h0 + c * 4 + 0), c1 = __ldg(h0 + c * 4 + 1);
    const float c2 = __ldg(h0 + c * 4 + 2), c3 = __ldg(h0 + c * 4 + 3);
    const float e0 = __ldg(h1 + c * 4 + 0), e1 = __ldg(h1 + c * 4 + 1);
    const float e2 = __ldg(h1 + c * 4 + 2), e3 = __ldg(h1 + c * 4 + 3);
    const float* wc = w + c * (DEPTH_N + 2);

    // x halo elements -1,-2,-3 via shuffle (lane 0 via scratch)
    float xm1, xm2, xm3;
    {
        float l14, h14, l15, h15;
        upk2(xp[14], l14, h14);
        upk2(xp[15], l15, h15);
        xm1 = __shfl_up_sync(0xffffffffu, h15, 1);
        xm2 = __shfl_up_sync(0xffffffffu, l15, 1);
        xm3 = __shfl_up_sync(0xffffffffu, h14, 1);
    }
    __syncthreads();
    if (lane == 0) {
        if (tid > 0) {
            xm1 = scr[3 * (warp - 1) + 2];
            xm2 = scr[3 * (warp - 1) + 1];
            xm3 = scr[3 * (warp - 1) + 0];
        } else { xm1 = 0.0f; xm2 = 0.0f; xm3 = 0.0f; }
    }

    const u64 a0 = pk2(c0, c0), a1 = pk2(c1, c1), a2 = pk2(c2, c2), a3 = pk2(c3, c3);

    // ---- level d=1 in pair form + y init ----
    // y = w13*x + w12*conv(x,h1,1) (w13 folded into tap-0 coeff); rl = conv(x,h0,1)
    {
        const float w13 = __ldg(wc + 13);
        const float w12 = __ldg(wc + 12);
        const u64 g0 = pk2(w12 * e0, w12 * e0);
        const u64 g1 = pk2(w12 * e1, w12 * e1);
        const u64 g2 = pk2(w12 * e2, w12 * e2);
        const float g3s = w13 + w12 * e3;
        const u64 g3 = pk2(g3s, g3s);
#pragma unroll
        for (int p = 0; p < NSLOT; ++p) {
            float lp, hp; upk2(xp[p], lp, hp); (void)hp;
            u64 t0 = xp[p];
            u64 t1, t2, t3;
            if (p >= 1) {
                float lpm, hpm; upk2(xp[p - 1], lpm, hpm);
                t1 = pk2(hpm, lp);
                t2 = xp[p - 1];
                if (p >= 2) {
                    float l2, h2; upk2(xp[p - 2], l2, h2); (void)l2;
                    t3 = pk2(h2, lpm);
                } else {
                    t3 = pk2(xm1, lpm);
                }
            } else {
                t1 = pk2(xm1, lp);
                t2 = pk2(xm2, xm1);
                t3 = pk2(xm3, xm2);
            }
            y2[p] = fma2(g3, t0, fma2(g2, t1, fma2(g1, t2, mul2(g0, t3))));
            rl[p] = fma2(a3, t0, fma2(a2, t1, fma2(a1, t2, mul2(a0, t3))));
        }
        // store only the slots d=2's remote taps read (slots 13..15)
#pragma unroll
        for (int p = 13; p < NSLOT; ++p)
            *(u64*)(blk0 + 8 * p) = rl[p];
    }

#define COEFFS(WI)                                                              \
        const float wi = __ldg(wc + (WI));                                      \
        const u64 b0 = pk2(wi * e0, wi * e0);                                   \
        const u64 b1 = pk2(wi * e1, wi * e1);                                   \
        const u64 b2 = pk2(wi * e2, wi * e2);                                   \
        const u64 b3 = pk2(wi * e3, wi * e3);

    // ---- Phase A: d=2,4,8,16 ----
    { COEFFS(11) levelA<1, 10>(rl, y2, blk0, blk1, ge1, ge2, a0, a1, a2, a3, b0, b1, b2, b3); }
    { COEFFS(10) levelA<2,  4>(rl, y2, blk1, blk0, ge1, ge2, a0, a1, a2, a3, b0, b1, b2, b3); }
    { COEFFS( 9) levelA<4,  0>(rl, y2, blk0, blk1, ge1, ge2, a0, a1, a2, a3, b0, b1, b2, b3); }
    { COEFFS( 8) levelA<8,  0>(rl, y2, blk1, blk0, ge1, ge2, a0, a1, a2, a3, b0, b1, b2, b3); }

    // ---- T1: block -> tile16 (y2 through smem; rl re-read from d=16's store) ----
    __syncthreads();
#pragma unroll
    for (int j = 0; j < NSLOT; ++j)
        *(u64*)(blk1 + 8 * j) = y2[j];
    __syncthreads();
#pragma unroll
    for (int j = 0; j < NSLOT; ++j) {
        y2[j] = *(const u64*)(til1 + 136 * j);
        rl[j] = *(const u64*)(til0 + 136 * j);
    }

    // ---- Phase B: d=32,64,128,256 ----
    { COEFFS(7) levelB<1, 10, true >(rl, y2, til0, til1, tge1, tge2, a0, a1, a2, a3, b0, b1, b2, b3); }
    { COEFFS(6) levelB<2,  4, true >(rl, y2, til1, til0, tge1, tge2, a0, a1, a2, a3, b0, b1, b2, b3); }
    { COEFFS(5) levelB<4,  0, true >(rl, y2, til0, til1, tge1, tge2, a0, a1, a2, a3, b0, b1, b2, b3); }
    { COEFFS(4) levelB<8,  0, true >(rl, y2, til1, til0, tge1, tge2, a0, a1, a2, a3, b0, b1, b2, b3); }

    // ---- T2: tile16 -> cyclic-256 ----
    __syncthreads();
#pragma unroll
    for (int j = 0; j < NSLOT; ++j)
        *(u64*)(til1 + 136 * j) = y2[j];
    __syncthreads();
#pragma unroll
    for (int k = 0; k < NSLOT; ++k) {
        y2[k] = *(const u64*)(cyc1 + 2176 * k);
        rl[k] = *(const u64*)(cyc0 + 2176 * k);
    }

    // ---- Phase C: d=512,1024,2048 — pure register ----
    { COEFFS(3) levelC<1>(rl, y2, a0, a1, a2, a3, b0, b1, b2, b3); }
    { COEFFS(2) levelC<2>(rl, y2, a0, a1, a2, a3, b0, b1, b2, b3); }
    { COEFFS(1) levelC<4>(rl, y2, a0, a1, a2, a3, b0, b1, b2, b3); }
#undef COEFFS

    // ---- final: y += w0*res_lo; tanh-GELU; coalesced STG.64 (cyclic) ----
    {
        const float w0v = __ldg(wc + 0);
        const u64 w0p = pk2(w0v, w0v);
        float2* o2 = (float2*)outr;
#pragma unroll
        for (int k = 0; k < NSLOT; ++k) {
            u64 yf = fma2(w0p, rl[k], y2[k]);
            float lo, hi; upk2(yf, lo, hi);
            o2[tid + 256 * k] = make_float2(gelu_t(lo), gelu_t(hi));
        }
    }
}

extern "C" void kernel_launch(void* const* d_in, const int* in_sizes, int n_in,
                              void* d_out, int out_size)
{
    (void)in_sizes; (void)n_in; (void)out_size;
    const float* x  = (const float*)d_in[0];
    const float* h0 = (const float*)d_in[1];
    const float* h1 = (const float*)d_in[2];
    const float* w  = (const float*)d_in[3];
    float* out = (float*)d_out;

    const int smem_bytes = 2 * BUFB + 128;   // 69,760 B
    cudaFuncSetAttribute(mr_kernel, cudaFuncAttributeMaxDynamicSharedMemorySize, smem_bytes);
    mr_kernel<<<B_N * C_CH, NTH, smem_bytes>>>(x, h0, h1, w, out);
}

// round 13
// speedup vs baseline: 1.1314x; 1.1314x over previous
#include <cuda_runtime.h>
#include <math.h>

#define B_N     16
#define C_CH    256
#define L_LEN   8192
#define DEPTH_N 12

#define NTH     256
#define NSLOT   16             // pairs per thread
#define SM_STRIDE 8704         // floats per buffer (8192 + 2 pad per 32 floats)
#define BUFB    (SM_STRIDE * 4)

using u64 = unsigned long long;

// padded relative word offset for element index e (may be < 0): e + 2*floor(e/32)
__host__ __device__ constexpr int padrel(int e) {
    int q = (e >= 0) ? (e / 32) : -(((31 - e) / 32));
    return e + 2 * q;
}

__device__ __forceinline__ u64 pk2(float lo, float hi) {
    u64 r; asm("mov.b64 %0,{%1,%2};" : "=l"(r) : "f"(lo), "f"(hi)); return r;
}
__device__ __forceinline__ void upk2(u64 v, float& lo, float& hi) {
    asm("mov.b64 {%0,%1},%2;" : "=f"(lo), "=f"(hi) : "l"(v));
}
__device__ __forceinline__ u64 fma2(u64 a, u64 b, u64 c) {
    u64 r; asm("fma.rn.f32x2 %0,%1,%2,%3;" : "=l"(r) : "l"(a), "l"(b), "l"(c)); return r;
}
__device__ __forceinline__ u64 mul2(u64 a, u64 b) {
    u64 r; asm("mul.rn.f32x2 %0,%1,%2;" : "=l"(r) : "l"(a), "l"(b)); return r;
}
// GELU via tanh-form with HW tanh.approx (1 MUFU op vs ~30-instr erff)
__device__ __forceinline__ float gelu_t(float x) {
    float s = x * fmaf(x * x, 0.044715f * 0.7978845608028654f, 0.7978845608028654f);
    float t; asm("tanh.approx.f32 %0,%1;" : "=f"(t) : "f"(s));
    return 0.5f * x * (1.0f + t);
}

// ---------- Phase A: block layout (thread owns pairs 16t..16t+15) ----------
template<int DD, int SF>
__device__ __forceinline__ void levelA(
    u64 (&rl)[NSLOT], u64 (&y2)[NSLOT], const char* ob, char* nb,
    bool ge1, bool ge2,
    u64 a0, u64 a1, u64 a2, u64 a3,
    u64 b0, u64 b1, u64 b2, u64 b3)
{
    __syncthreads();   // previous level's smem writes visible
#pragma unroll
    for (int p = NSLOT - 1; p >= 0; --p) {
        u64 t0 = rl[p];
        u64 t1, t2, t3;
        if (p >= 1 * DD) t1 = rl[p - 1 * DD];
        else { bool ok = ((1 * DD - p + 15) / 16 <= 1) ? ge1 : ge2;
               t1 = ok ? *(const u64*)(ob + 4 * padrel(2 * (p - 1 * DD))) : 0; }
        if (p >= 2 * DD) t2 = rl[p - 2 * DD];
        else { bool ok = ((2 * DD - p + 15) / 16 <= 1) ? ge1 : ge2;
               t2 = ok ? *(const u64*)(ob + 4 * padrel(2 * (p - 2 * DD))) : 0; }
        if (p >= 3 * DD) t3 = rl[p - 3 * DD];
        else { bool ok = ((3 * DD - p + 15) / 16 <= 1) ? ge1 : ge2;
               t3 = ok ? *(const u64*)(ob + 4 * padrel(2 * (p - 3 * DD))) : 0; }
        y2[p] = fma2(b3, t0, fma2(b2, t1, fma2(b1, t2, fma2(b0, t3, y2[p]))));
        rl[p] = fma2(a3, t0, fma2(a2, t1, fma2(a1, t2, mul2(a0, t3))));
    }
#pragma unroll
    for (int p = SF; p < NSLOT; ++p)
        *(u64*)(nb + 8 * p) = rl[p];
}

// ---------- Phase B: tile16 layout (thread (T,r) owns pairs 256T + r + 16j) ----------
template<int DJ, int SF, bool STORE>
__device__ __forceinline__ void levelB(
    u64 (&rl)[NSLOT], u64 (&y2)[NSLOT], const char* ob, char* nb,
    bool tge1, bool tge2,
    u64 a0, u64 a1, u64 a2, u64 a3,
    u64 b0, u64 b1, u64 b2, u64 b3)
{
    __syncthreads();
#pragma unroll
    for (int j = NSLOT - 1; j >= 0; --j) {
        u64 t0 = rl[j];
        u64 t1, t2, t3;
        if (j >= 1 * DJ) t1 = rl[j - 1 * DJ];
        else { bool ok = (1 * DJ - j <= 16) ? tge1 : tge2;
               t1 = ok ? *(const u64*)(ob + 136 * (j - 1 * DJ)) : 0; }
        if (j >= 2 * DJ) t2 = rl[j - 2 * DJ];
        else { bool ok = (2 * DJ - j <= 16) ? tge1 : tge2;
               t2 = ok ? *(const u64*)(ob + 136 * (j - 2 * DJ)) : 0; }
        if (j >= 3 * DJ) t3 = rl[j - 3 * DJ];
        else { bool ok = (3 * DJ - j <= 16) ? tge1 : tge2;
               t3 = ok ? *(const u64*)(ob + 136 * (j - 3 * DJ)) : 0; }
        y2[j] = fma2(b3, t0, fma2(b2, t1, fma2(b1, t2, fma2(b0, t3, y2[j]))));
        rl[j] = fma2(a3, t0, fma2(a2, t1, fma2(a1, t2, mul2(a0, t3))));
    }
    if (STORE) {
#pragma unroll
        for (int j = SF; j < NSLOT; ++j)
            *(u64*)(nb + 136 * j) = rl[j];
    }
}

// ---------- Phase C: cyclic-256 layout (pure register, no smem, no sync) ----------
template<int DK>
__device__ __forceinline__ void levelC(
    u64 (&rl)[NSLOT], u64 (&y2)[NSLOT],
    u64 a0, u64 a1, u64 a2, u64 a3,
    u64 b0, u64 b1, u64 b2, u64 b3)
{
#pragma unroll
    for (int k = NSLOT - 1; k >= 0; --k) {
        u64 t0 = rl[k];
        u64 t1 = (k >= 1 * DK) ? rl[k - 1 * DK] : 0;
        u64 t2 = (k >= 2 * DK) ? rl[k - 2 * DK] : 0;
        u64 t3 = (k >= 3 * DK) ? rl[k - 3 * DK] : 0;
        y2[k] = fma2(b3, t0, fma2(b2, t1, fma2(b1, t2, fma2(b0, t3, y2[k]))));
        rl[k] = fma2(a3, t0, fma2(a2, t1, fma2(a1, t2, mul2(a0, t3))));
    }
}

__global__ void __launch_bounds__(NTH, 3)
mr_kernel(const float* __restrict__ x, const float* __restrict__ h0,
          const float* __restrict__ h1, const float* __restrict__ w,
          float* __restrict__ out)
{
    extern __shared__ float sm[];
    char* B0 = (char*)sm;
    char* B1 = (char*)sm + BUFB;

    const int tid  = threadIdx.x;
    const int T    = tid >> 4;        // tile index (tile16 layout)
    const int rr   = tid & 15;        // lane-in-tile
    const int row  = blockIdx.x;      // b*C + c
    const int c    = row & (C_CH - 1);
    const float* xr   = x   + (size_t)row * L_LEN;
    float*       outr = out + (size_t)row * L_LEN;

    const bool ge1  = (tid >= 1), ge2 = (tid >= 2);
    const bool tge1 = (T >= 1),  tge2 = (T >= 2);

    char* blk0 = B0 + 136 * tid;
    char* blk1 = B1 + 136 * tid;
    char* til0 = B0 + 2176 * T + 8 * rr;
    char* til1 = B1 + 2176 * T + 8 * rr;
    char* cyc0 = B0 + 8 * tid + 8 * (tid >> 4);
    char* cyc1 = B1 + 8 * tid + 8 * (tid >> 4);

    // ---- stage x -> B0 (padded pair layout) with COALESCED LDG.128 ----
    // Lane stride 16B -> 4 lines per LDG (vs 32 divergent before).
    // STS addresses: byte = 16*tid + 8*(tid>>3) + 4352*i -> conflict-free .64.
    {
        const float4* x4 = (const float4*)xr;
        char* dst = B0 + 16 * tid + 8 * (tid >> 3);
#pragma unroll
        for (int i = 0; i < 8; ++i) {
            float4 v = x4[tid + 256 * i];
            *(u64*)(dst + 4352 * i)     = pk2(v.x, v.y);
            *(u64*)(dst + 4352 * i + 8) = pk2(v.z, v.w);
        }
    }

    // ---- per-channel coefficients (overlap with staging latency) ----
    const float c0 = __ldg(h0 + c * 4 + 0), c1 = __ldg(h0 + c * 4 + 1);
    const float c2 = __ldg(h0 + c * 4 + 2), c3 = __ldg(h0 + c * 4 + 3);
    const float e0 = __ldg(h1 + c * 4 + 0), e1 = __ldg(h1 + c * 4 + 1);
    const float e2 = __ldg(h1 + c * 4 + 2), e3 = __ldg(h1 + c * 4 + 3);
    const float* wc = w + c * (DEPTH_N + 2);

    __syncthreads();   // staged x visible

    // ---- reload own 32 elements as 16 pairs (conflict-free LDS.64) ----
    u64 rl[NSLOT], y2[NSLOT];
    u64 xp[NSLOT];
#pragma unroll
    for (int p = 0; p < NSLOT; ++p)
        xp[p] = *(const u64*)(blk0 + 8 * p);

    // x halo x[-1],x[-2],x[-3] from left neighbor's block (bytes -12,-16,-20)
    float xm1 = ge1 ? *(const float*)(blk0 - 12) : 0.0f;
    float xm2 = ge1 ? *(const float*)(blk0 - 16) : 0.0f;
    float xm3 = ge1 ? *(const float*)(blk0 - 20) : 0.0f;

    const u64 a0 = pk2(c0, c0), a1 = pk2(c1, c1), a2 = pk2(c2, c2), a3 = pk2(c3, c3);

    // ---- level d=1 in pair form + y init ----
    // y = w13*x + w12*conv(x,h1,1) (w13 folded into tap-0 coeff); rl = conv(x,h0,1)
    // NOTE: rl now stored to B1 (x occupies B0) -> ping-pong parity flipped below.
    {
        const float w13 = __ldg(wc + 13);
        const float w12 = __ldg(wc + 12);
        const u64 g0 = pk2(w12 * e0, w12 * e0);
        const u64 g1 = pk2(w12 * e1, w12 * e1);
        const u64 g2 = pk2(w12 * e2, w12 * e2);
        const float g3s = w13 + w12 * e3;
        const u64 g3 = pk2(g3s, g3s);
#pragma unroll
        for (int p = 0; p < NSLOT; ++p) {
            float lp, hp; upk2(xp[p], lp, hp); (void)hp;
            u64 t0 = xp[p];
            u64 t1, t2, t3;
            if (p >= 1) {
                float lpm, hpm; upk2(xp[p - 1], lpm, hpm);
                t1 = pk2(hpm, lp);
                t2 = xp[p - 1];
                if (p >= 2) {
                    float l2, h2; upk2(xp[p - 2], l2, h2); (void)l2;
                    t3 = pk2(h2, lpm);
                } else {
                    t3 = pk2(xm1, lpm);
                }
            } else {
                t1 = pk2(xm1, lp);
                t2 = pk2(xm2, xm1);
                t3 = pk2(xm3, xm2);
            }
            y2[p] = fma2(g3, t0, fma2(g2, t1, fma2(g1, t2, mul2(g0, t3))));
            rl[p] = fma2(a3, t0, fma2(a2, t1, fma2(a1, t2, mul2(a0, t3))));
        }
        // store only the slots d=2's remote taps read (slots 13..15) -> B1
#pragma unroll
        for (int p = 13; p < NSLOT; ++p)
            *(u64*)(blk1 + 8 * p) = rl[p];
    }

#define COEFFS(WI)                                                              \
        const float wi = __ldg(wc + (WI));                                      \
        const u64 b0 = pk2(wi * e0, wi * e0);                                   \
        const u64 b1 = pk2(wi * e1, wi * e1);                                   \
        const u64 b2 = pk2(wi * e2, wi * e2);                                   \
        const u64 b3 = pk2(wi * e3, wi * e3);

    // ---- Phase A: d=2,4,8,16 (parity flipped: L1's rl is in B1) ----
    // d=2 stores to B0 clobber staged x; safe: levelA's entry sync orders all
    // L1 x-reads before any d=2 store.
    { COEFFS(11) levelA<1, 10>(rl, y2, blk1, blk0, ge1, ge2, a0, a1, a2, a3, b0, b1, b2, b3); }
    { COEFFS(10) levelA<2,  4>(rl, y2, blk0, blk1, ge1, ge2, a0, a1, a2, a3, b0, b1, b2, b3); }
    { COEFFS( 9) levelA<4,  0>(rl, y2, blk1, blk0, ge1, ge2, a0, a1, a2, a3, b0, b1, b2, b3); }
    { COEFFS( 8) levelA<8,  0>(rl, y2, blk0, blk1, ge1, ge2, a0, a1, a2, a3, b0, b1, b2, b3); }

    // ---- T1: block -> tile16 (rl in B1 after d=16; stage y2 through B0) ----
    __syncthreads();
#pragma unroll
    for (int j = 0; j < NSLOT; ++j)
        *(u64*)(blk0 + 8 * j) = y2[j];
    __syncthreads();
#pragma unroll
    for (int j = 0; j < NSLOT; ++j) {
        y2[j] = *(const u64*)(til0 + 136 * j);
        rl[j] = *(const u64*)(til1 + 136 * j);
    }

    // ---- Phase B: d=32,64,128,256 (rl currently sourced from B1) ----
    { COEFFS(7) levelB<1, 10, true >(rl, y2, til1, til0, tge1, tge2, a0, a1, a2, a3, b0, b1, b2, b3); }
    { COEFFS(6) levelB<2,  4, true >(rl, y2, til0, til1, tge1, tge2, a0, a1, a2, a3, b0, b1, b2, b3); }
    { COEFFS(5) levelB<4,  0, true >(rl, y2, til1, til0, tge1, tge2, a0, a1, a2, a3, b0, b1, b2, b3); }
    { COEFFS(4) levelB<8,  0, true >(rl, y2, til0, til1, tge1, tge2, a0, a1, a2, a3, b0, b1, b2, b3); }

    // ---- T2: tile16 -> cyclic-256 (rl in B1 after d=256; stage y2 via B0) ----
    __syncthreads();
#pragma unroll
    for (int j = 0; j < NSLOT; ++j)
        *(u64*)(til0 + 136 * j) = y2[j];
    __syncthreads();
#pragma unroll
    for (int k = 0; k < NSLOT; ++k) {
        y2[k] = *(const u64*)(cyc0 + 2176 * k);
        rl[k] = *(const u64*)(cyc1 + 2176 * k);
    }

    // ---- Phase C: d=512,1024,2048 — pure register ----
    { COEFFS(3) levelC<1>(rl, y2, a0, a1, a2, a3, b0, b1, b2, b3); }
    { COEFFS(2) levelC<2>(rl, y2, a0, a1, a2, a3, b0, b1, b2, b3); }
    { COEFFS(1) levelC<4>(rl, y2, a0, a1, a2, a3, b0, b1, b2, b3); }
#undef COEFFS

    // ---- final: y += w0*res_lo; tanh-GELU; coalesced STG.64 (cyclic) ----
    {
        const float w0v = __ldg(wc + 0);
        const u64 w0p = pk2(w0v, w0v);
        float2* o2 = (float2*)outr;
#pragma unroll
        for (int k = 0; k < NSLOT; ++k) {
            u64 yf = fma2(w0p, rl[k], y2[k]);
            float lo, hi; upk2(yf, lo, hi);
            o2[tid + 256 * k] = make_float2(gelu_t(lo), gelu_t(hi));
        }
    }
}

extern "C" void kernel_launch(void* const* d_in, const int* in_sizes, int n_in,
                              void* d_out, int out_size)
{
    (void)in_sizes; (void)n_in; (void)out_size;
    const float* x  = (const float*)d_in[0];
    const float* h0 = (const float*)d_in[1];
    const float* h1 = (const float*)d_in[2];
    const float* w  = (const float*)d_in[3];
    float* out = (float*)d_out;

    const int smem_bytes = 2 * BUFB;   // 69,632 B (x3 CTAs = 209KB <= 228KB)
    cudaFuncSetAttribute(mr_kernel, cudaFuncAttributeMaxDynamicSharedMemorySize, smem_bytes);
    mr_kernel<<<B_N * C_CH, NTH, smem_bytes>>>(x, h0, h1, w, out);
}